// round 4
// baseline (speedup 1.0000x reference)
#include <cuda_runtime.h>
#include <cfloat>

#define BB   8
#define NN   8192
#define DD   64
#define SS   1024
#define KNB  16          // NSAMPLE
#define WNC  16          // weightnet out channels
#define OUTC 128
#define CINC 67          // 3 + D
#define AGGW (CINC*WNC)  // 1072

#define OFF_OUT (BB*3*SS)                 // 24576
#define OFF_IDX (BB*3*SS + BB*OUTC*SS)    // 1073152

// ---------------- scratch: ONE static device buffer, no allocation ----------------
#define SC_XYZT   0
#define SC_PTST   (SC_XYZT + BB*NN*4)
#define SC_NEWXYZ (SC_PTST + BB*NN*DD)
#define SC_KNN    (SC_NEWXYZ + BB*SS*3)
#define SC_AGG    (SC_KNN + BB*SS*KNB)
#define SC_TOTAL  (SC_AGG + (size_t)BB*SS*AGGW)

__device__ __align__(16) float g_scratch[SC_TOTAL];

#define g_xyzT4  ((float4*)(g_scratch + SC_XYZT))
#define g_ptsT   (g_scratch + SC_PTST)
#define g_newxyz (g_scratch + SC_NEWXYZ)
#define g_knn    ((int*)(g_scratch + SC_KNN))
#define g_agg    (g_scratch + SC_AGG)

// ---------------- layout transforms ----------------
__global__ void xyzT_kernel(const float* __restrict__ xyz) {
    int i = blockIdx.x * 256 + threadIdx.x;     // 0 .. BB*NN-1
    int b = i >> 13, n = i & (NN - 1);
    const float* X = xyz + (size_t)b * 3 * NN;
    g_xyzT4[i] = make_float4(X[n], X[NN + n], X[2 * NN + n], 0.f);
}

__global__ void ptsT_kernel(const float* __restrict__ pts) {
    __shared__ float tile[32][33];
    int b = blockIdx.z;
    int n0 = blockIdx.x * 32, d0 = blockIdx.y * 32;
    int tx = threadIdx.x, ty = threadIdx.y;
    #pragma unroll
    for (int i = 0; i < 32; i += 8)
        tile[ty + i][tx] = pts[(size_t)b * DD * NN + (size_t)(d0 + ty + i) * NN + n0 + tx];
    __syncthreads();
    #pragma unroll
    for (int i = 0; i < 32; i += 8)
        g_ptsT[((size_t)b * NN + n0 + ty + i) * DD + d0 + tx] = tile[tx][ty + i];
}

// ---------------- FPS: 1 block per batch, 1024 threads, 8 pts/thread ----------------
__global__ void __launch_bounds__(1024, 1) fps_kernel(float* __restrict__ dout) {
    int b = blockIdx.x;
    int t = threadIdx.x;
    int lane = t & 31, warp = t >> 5;

    float px[8], py[8], pz[8], dist[8];
    #pragma unroll
    for (int j = 0; j < 8; j++) {
        float4 p = g_xyzT4[b * NN + t + (j << 10)];
        px[j] = p.x; py[j] = p.y; pz[j] = p.z;
        dist[j] = 1e10f;
    }

    __shared__ float s_bd[32];
    __shared__ int   s_bi[32];
    __shared__ int   s_far;

    int far = 0;
    for (int s = 0; s < SS; s++) {
        float4 c = g_xyzT4[b * NN + far];   // broadcast load (L1-resident after warmup)
        if (t == 0) {
            dout[b * 3 * SS + s]          = c.x;
            dout[b * 3 * SS + SS + s]     = c.y;
            dout[b * 3 * SS + 2 * SS + s] = c.z;
            dout[OFF_IDX + b * SS + s]    = (float)far;
            int gs = (b * SS + s) * 3;
            g_newxyz[gs] = c.x; g_newxyz[gs + 1] = c.y; g_newxyz[gs + 2] = c.z;
        }
        float bd = -1.f; int bi = 0;
        #pragma unroll
        for (int j = 0; j < 8; j++) {
            // EXACT fp32, no FMA contraction, left-to-right sum (match reference)
            float dx = __fsub_rn(px[j], c.x);
            float dy = __fsub_rn(py[j], c.y);
            float dz = __fsub_rn(pz[j], c.z);
            float d  = __fadd_rn(__fadd_rn(__fmul_rn(dx, dx), __fmul_rn(dy, dy)),
                                 __fmul_rn(dz, dz));
            float nd = fminf(dist[j], d);
            dist[j] = nd;
            if (nd > bd) { bd = nd; bi = t + (j << 10); }  // ascending idx -> first-max kept
        }
        // warp reduce: larger d wins, tie -> smaller index (argmax first-occurrence)
        #pragma unroll
        for (int off = 16; off; off >>= 1) {
            float od = __shfl_down_sync(0xffffffffu, bd, off);
            int   oi = __shfl_down_sync(0xffffffffu, bi, off);
            if (od > bd || (od == bd && oi < bi)) { bd = od; bi = oi; }
        }
        if (lane == 0) { s_bd[warp] = bd; s_bi[warp] = bi; }
        __syncthreads();
        if (warp == 0) {
            bd = s_bd[lane]; bi = s_bi[lane];
            #pragma unroll
            for (int off = 16; off; off >>= 1) {
                float od = __shfl_down_sync(0xffffffffu, bd, off);
                int   oi = __shfl_down_sync(0xffffffffu, bi, off);
                if (od > bd || (od == bd && oi < bi)) { bd = od; bi = oi; }
            }
            if (lane == 0) s_far = bi;
        }
        __syncthreads();
        far = s_far;
    }
}

// ---------------- KNN: 1 warp per sampled point, 4 candidates per iteration ----------------
__global__ void __launch_bounds__(128) knn_kernel() {
    __shared__ float sd[4][32][17];
    __shared__ int   si[4][32][17];
    int w = threadIdx.x >> 5, lane = threadIdx.x & 31;
    int gid = blockIdx.x * 4 + w;          // 0..8191
    int b = gid >> 10;

    float qx = g_newxyz[gid * 3], qy = g_newxyz[gid * 3 + 1], qz = g_newxyz[gid * 3 + 2];
    const float4* X4 = g_xyzT4 + b * NN;

    float nd[16]; int ni[16];
    #pragma unroll
    for (int j = 0; j < 16; j++) { nd[j] = FLT_MAX; ni[j] = 0x7FFFFFFF; }

    for (int i = lane; i < NN; i += 128) {   // 4 points per iter -> MLP 4
        float4 p[4];
        #pragma unroll
        for (int u = 0; u < 4; u++) p[u] = X4[i + u * 32];
        #pragma unroll
        for (int u = 0; u < 4; u++) {
            float dx = __fsub_rn(qx, p[u].x);
            float dy = __fsub_rn(qy, p[u].y);
            float dz = __fsub_rn(qz, p[u].z);
            float d  = __fadd_rn(__fadd_rn(__fmul_rn(dx, dx), __fmul_rn(dy, dy)),
                                 __fmul_rn(dz, dz));
            if (d < nd[15]) {      // strict <: equal dist keeps earlier (smaller) index
                float cd = d; int ci = i + u * 32;
                #pragma unroll
                for (int j = 0; j < 16; j++) {
                    if (cd < nd[j]) {
                        float td = nd[j]; int ti = ni[j];
                        nd[j] = cd; ni[j] = ci; cd = td; ci = ti;
                    }
                }
            }
        }
    }
    #pragma unroll
    for (int j = 0; j < 16; j++) { sd[w][lane][j] = nd[j]; si[w][lane][j] = ni[j]; }
    __syncwarp();

    // 16-round multiway merge of 32 sorted lists (dist asc, tie -> smaller idx)
    int p = 0;
    for (int r = 0; r < 16; r++) {
        float hd = (p < 16) ? sd[w][lane][p] : FLT_MAX;
        int   hi = (p < 16) ? si[w][lane][p] : 0x7FFFFFFF;
        #pragma unroll
        for (int off = 16; off; off >>= 1) {
            float od = __shfl_xor_sync(0xffffffffu, hd, off);
            int   oi = __shfl_xor_sync(0xffffffffu, hi, off);
            if (od < hd || (od == hd && oi < hi)) { hd = od; hi = oi; }
        }
        if (p < 16 && si[w][lane][p] == hi) p++;   // global indices unique -> exact winner
        if (lane == 0) g_knn[gid * 16 + r] = hi;
    }
}

// ---------------- gather + WeightNet MLP + einsum agg: 1 block per point ----------------
__global__ void __launch_bounds__(128) agg_kernel(
    const float* __restrict__ w1, const float* __restrict__ b1,
    const float* __restrict__ w2, const float* __restrict__ b2,
    const float* __restrict__ w3, const float* __restrict__ b3)
{
    __shared__ float feat[KNB][CINC + 1];   // pad to 68
    __shared__ float wts[KNB][WNC];
    __shared__ int   nn[KNB];
    __shared__ float q[3];

    int t = threadIdx.x;
    int pid = blockIdx.x;
    int b = pid >> 10;

    if (t < KNB) nn[t] = g_knn[pid * KNB + t];
    if (t < 3)   q[t]  = g_newxyz[pid * 3 + t];
    __syncthreads();

    if (t < KNB) {
        float4 pp = g_xyzT4[b * NN + nn[t]];
        float gx = pp.x - q[0], gy = pp.y - q[1], gz = pp.z - q[2];
        feat[t][0] = gx; feat[t][1] = gy; feat[t][2] = gz;
        float h1[8], h2[8];
        #pragma unroll
        for (int j = 0; j < 8; j++) {
            float a = b1[j];
            a = fmaf(gx, w1[j], a);
            a = fmaf(gy, w1[8 + j], a);
            a = fmaf(gz, w1[16 + j], a);
            h1[j] = fmaxf(a, 0.f);
        }
        #pragma unroll
        for (int j = 0; j < 8; j++) {
            float a = b2[j];
            #pragma unroll
            for (int i = 0; i < 8; i++) a = fmaf(h1[i], w2[i * 8 + j], a);
            h2[j] = fmaxf(a, 0.f);
        }
        #pragma unroll
        for (int j = 0; j < 16; j++) {
            float a = b3[j];
            #pragma unroll
            for (int i = 0; i < 8; i++) a = fmaf(h2[i], w3[i * 16 + j], a);
            wts[t][j] = fmaxf(a, 0.f);
        }
    }
    // gather neighbor point features (rows contiguous thanks to ptsT)
    for (int idx = t; idx < KNB * DD; idx += 128) {
        int k = idx >> 6, d = idx & 63;
        feat[k][3 + d] = g_ptsT[((size_t)b * NN + nn[k]) * DD + d];
    }
    __syncthreads();

    // agg[c][w] = sum_k feat[k][c] * wts[k][w], flattened j = c*16 + w
    for (int j = t; j < AGGW; j += 128) {
        int c = j >> 4, w = j & 15;
        float a = 0.f;
        #pragma unroll
        for (int k = 0; k < KNB; k++) a = fmaf(feat[k][c], wts[k][w], a);
        g_agg[(size_t)pid * AGGW + j] = a;
    }
}

// ---------------- final linear: GEMM [8192 x 1072] * [1072 x 128] + bias + leaky ----------------
__global__ void __launch_bounds__(256) gemm_kernel(
    const float* __restrict__ lin_w, const float* __restrict__ lin_b,
    float* __restrict__ dout)
{
    __shared__ float As[64][16];
    __shared__ float Bs[16][128];
    int t = threadIdx.x;
    int row0 = blockIdx.x * 64;
    int cg = t & 31, rg = t >> 5;    // 32 col-groups x 8 row-groups

    float acc[8][4];
    #pragma unroll
    for (int i = 0; i < 8; i++)
        #pragma unroll
        for (int j = 0; j < 4; j++) acc[i][j] = 0.f;

    for (int k0 = 0; k0 < AGGW; k0 += 16) {
        __syncthreads();
        {
            int r = t >> 2, kk = (t & 3) << 2;
            float4 v = *(const float4*)&g_agg[(size_t)(row0 + r) * AGGW + k0 + kk];
            *(float4*)&As[r][kk] = v;
        }
        {
            int kk = t >> 5, c = (t & 31) << 2;
            *(float4*)&Bs[kk][c]     = *(const float4*)&lin_w[(size_t)(k0 + kk) * 128 + c];
            *(float4*)&Bs[kk + 8][c] = *(const float4*)&lin_w[(size_t)(k0 + kk + 8) * 128 + c];
        }
        __syncthreads();
        #pragma unroll
        for (int kk = 0; kk < 16; kk++) {
            float4 bv = *(float4*)&Bs[kk][cg << 2];
            #pragma unroll
            for (int ri = 0; ri < 8; ri++) {
                float av = As[rg * 8 + ri][kk];
                acc[ri][0] = fmaf(av, bv.x, acc[ri][0]);
                acc[ri][1] = fmaf(av, bv.y, acc[ri][1]);
                acc[ri][2] = fmaf(av, bv.z, acc[ri][2]);
                acc[ri][3] = fmaf(av, bv.w, acc[ri][3]);
            }
        }
    }
    float bias[4];
    #pragma unroll
    for (int ci = 0; ci < 4; ci++) bias[ci] = lin_b[(cg << 2) + ci];
    #pragma unroll
    for (int ri = 0; ri < 8; ri++) {
        int p = row0 + rg * 8 + ri;
        int b = p >> 10, s = p & 1023;
        #pragma unroll
        for (int ci = 0; ci < 4; ci++) {
            int c = (cg << 2) + ci;
            float v = acc[ri][ci] + bias[ci];
            v = (v > 0.f) ? v : 0.1f * v;             // LeakyReLU(0.1)
            dout[OFF_OUT + ((size_t)b * OUTC + c) * SS + s] = v;
        }
    }
}

// ---------------- launch ----------------
extern "C" void kernel_launch(void* const* d_in, const int* in_sizes, int n_in,
                              void* d_out, int out_size) {
    const float* xyz = (const float*)d_in[0];
    const float* pts = (const float*)d_in[1];
    const float* w1  = (const float*)d_in[2];
    const float* b1  = (const float*)d_in[3];
    const float* w2  = (const float*)d_in[4];
    const float* b2  = (const float*)d_in[5];
    const float* w3  = (const float*)d_in[6];
    const float* b3  = (const float*)d_in[7];
    const float* lw  = (const float*)d_in[8];
    const float* lb  = (const float*)d_in[9];
    float* out = (float*)d_out;

    xyzT_kernel<<<BB * NN / 256, 256>>>(xyz);
    ptsT_kernel<<<dim3(NN / 32, DD / 32, BB), dim3(32, 8)>>>(pts);
    fps_kernel<<<BB, 1024>>>(out);
    knn_kernel<<<BB * SS / 4, 128>>>();
    agg_kernel<<<BB * SS, 128>>>(w1, b1, w2, b2, w3, b3);
    gemm_kernel<<<BB * SS / 64, 256>>>(lw, lb, out);
}

// round 5
// speedup vs baseline: 1.4530x; 1.4530x over previous
#include <cuda_runtime.h>
#include <cfloat>

#define BB   8
#define NN   8192
#define DD   64
#define SS   1024
#define KNB  16          // NSAMPLE
#define WNC  16          // weightnet out channels
#define OUTC 128
#define CINC 67          // 3 + D
#define AGGW (CINC*WNC)  // 1072

#define OFF_OUT (BB*3*SS)                 // 24576
#define OFF_IDX (BB*3*SS + BB*OUTC*SS)    // 1073152

// ---------------- scratch: ONE static device buffer, no allocation ----------------
#define SC_XYZT   0
#define SC_PTST   (SC_XYZT + BB*NN*4)
#define SC_NEWXYZ (SC_PTST + BB*NN*DD)
#define SC_KNN    (SC_NEWXYZ + BB*SS*3)
#define SC_AGG    (SC_KNN + BB*SS*KNB)
#define SC_TOTAL  (SC_AGG + (size_t)BB*SS*AGGW)

__device__ __align__(16) float g_scratch[SC_TOTAL];

#define g_xyzT4  ((float4*)(g_scratch + SC_XYZT))
#define g_ptsT   (g_scratch + SC_PTST)
#define g_newxyz (g_scratch + SC_NEWXYZ)
#define g_knn    ((int*)(g_scratch + SC_KNN))
#define g_agg    (g_scratch + SC_AGG)

// ---------------- packed f32x2 helpers (Blackwell, exact per-element rn) ----------------
__device__ __forceinline__ unsigned long long pk2(float lo, float hi) {
    unsigned long long r;
    asm("mov.b64 %0, {%1, %2};" : "=l"(r) : "f"(lo), "f"(hi));
    return r;
}
__device__ __forceinline__ void upk2(unsigned long long v, float& lo, float& hi) {
    asm("mov.b64 {%0, %1}, %2;" : "=f"(lo), "=f"(hi) : "l"(v));
}
__device__ __forceinline__ unsigned long long addx2(unsigned long long a, unsigned long long b) {
    unsigned long long r;
    asm("add.rn.f32x2 %0, %1, %2;" : "=l"(r) : "l"(a), "l"(b));
    return r;
}
__device__ __forceinline__ unsigned long long mulx2(unsigned long long a, unsigned long long b) {
    unsigned long long r;
    asm("mul.rn.f32x2 %0, %1, %2;" : "=l"(r) : "l"(a), "l"(b));
    return r;
}

// ---------------- layout transforms ----------------
__global__ void xyzT_kernel(const float* __restrict__ xyz) {
    int i = blockIdx.x * 256 + threadIdx.x;     // 0 .. BB*NN-1
    int b = i >> 13, n = i & (NN - 1);
    const float* X = xyz + (size_t)b * 3 * NN;
    g_xyzT4[i] = make_float4(X[n], X[NN + n], X[2 * NN + n], 0.f);
}

__global__ void ptsT_kernel(const float* __restrict__ pts) {
    __shared__ float tile[32][33];
    int b = blockIdx.z;
    int n0 = blockIdx.x * 32, d0 = blockIdx.y * 32;
    int tx = threadIdx.x, ty = threadIdx.y;
    #pragma unroll
    for (int i = 0; i < 32; i += 8)
        tile[ty + i][tx] = pts[(size_t)b * DD * NN + (size_t)(d0 + ty + i) * NN + n0 + tx];
    __syncthreads();
    #pragma unroll
    for (int i = 0; i < 32; i += 8)
        g_ptsT[((size_t)b * NN + n0 + ty + i) * DD + d0 + tx] = tile[tx][ty + i];
}

// ---------------- FPS: 1 block per batch, 1024 threads, 8 pts/thread ----------------
// packed f32x2 distance math (exact rn per element), REDUX argmax reductions.
__global__ void __launch_bounds__(1024, 1) fps_kernel(float* __restrict__ dout) {
    int b = blockIdx.x;
    int t = threadIdx.x;
    int lane = t & 31, warp = t >> 5;

    // pair layout: pair j holds points t + (2j)*1024 and t + (2j+1)*1024
    unsigned long long ppx[4], ppy[4], ppz[4];
    float dist[8];
    #pragma unroll
    for (int j = 0; j < 4; j++) {
        float4 p0 = g_xyzT4[b * NN + t + ((2 * j) << 10)];
        float4 p1 = g_xyzT4[b * NN + t + ((2 * j + 1) << 10)];
        ppx[j] = pk2(p0.x, p1.x);
        ppy[j] = pk2(p0.y, p1.y);
        ppz[j] = pk2(p0.z, p1.z);
        dist[2 * j] = 1e10f; dist[2 * j + 1] = 1e10f;
    }

    __shared__ float s_bd[32];
    __shared__ unsigned s_bi[32];
    __shared__ int s_far;

    int far = 0;
    for (int s = 0; s < SS; s++) {
        float4 c = g_xyzT4[b * NN + far];   // broadcast load (L1-resident)
        if (t == 0) {
            dout[b * 3 * SS + s]          = c.x;
            dout[b * 3 * SS + SS + s]     = c.y;
            dout[b * 3 * SS + 2 * SS + s] = c.z;
            dout[OFF_IDX + b * SS + s]    = (float)far;
            int gs = (b * SS + s) * 3;
            g_newxyz[gs] = c.x; g_newxyz[gs + 1] = c.y; g_newxyz[gs + 2] = c.z;
        }
        // negated centroid, packed (exact: rn-add of -c == rn-sub of c)
        unsigned long long ncx = pk2(-c.x, -c.x);
        unsigned long long ncy = pk2(-c.y, -c.y);
        unsigned long long ncz = pk2(-c.z, -c.z);

        float bd = 0.0f; unsigned bi = 0x7fffffffu;
        #pragma unroll
        for (int j = 0; j < 4; j++) {
            unsigned long long dx = addx2(ppx[j], ncx);
            unsigned long long dy = addx2(ppy[j], ncy);
            unsigned long long dz = addx2(ppz[j], ncz);
            unsigned long long xx = mulx2(dx, dx);
            unsigned long long yy = mulx2(dy, dy);
            unsigned long long s1 = addx2(xx, yy);
            unsigned long long zz = mulx2(dz, dz);
            unsigned long long dd = addx2(s1, zz);
            float d0, d1;
            upk2(dd, d0, d1);
            float n0 = fminf(dist[2 * j], d0);     dist[2 * j] = n0;
            if (n0 > bd) { bd = n0; bi = (unsigned)(t + ((2 * j) << 10)); }
            float n1 = fminf(dist[2 * j + 1], d1); dist[2 * j + 1] = n1;
            if (n1 > bd) { bd = n1; bi = (unsigned)(t + ((2 * j + 1) << 10)); }
        }
        // warp argmax via REDUX: dist >= 0 so float bits order as u32; tie -> min index
        unsigned mb   = __float_as_uint(bd);
        unsigned wmax = __reduce_max_sync(0xffffffffu, mb);
        unsigned cand = (mb == wmax) ? bi : 0xffffffffu;
        unsigned wbi  = __reduce_min_sync(0xffffffffu, cand);
        if (lane == 0) { s_bd[warp] = __uint_as_float(wmax); s_bi[warp] = wbi; }
        __syncthreads();
        if (warp == 0) {
            unsigned vb = __float_as_uint(s_bd[lane]);
            unsigned vi = s_bi[lane];
            unsigned gmax = __reduce_max_sync(0xffffffffu, vb);
            unsigned gc   = (vb == gmax) ? vi : 0xffffffffu;
            unsigned gbi  = __reduce_min_sync(0xffffffffu, gc);
            if (lane == 0) s_far = (int)gbi;
        }
        __syncthreads();
        far = s_far;
    }
}

// ---------------- KNN: 1 warp per sampled point, warp-wide tau gating ----------------
// tau = min over lanes of nd[15] is a conservative (>= exact) bound on the warp-wide
// 16th-smallest-so-far, so gating insertion on d < tau never drops a final top-16
// member; it makes the (warp-divergent) 16-deep insertion chain rare.
__global__ void __launch_bounds__(256) knn_kernel() {
    __shared__ float sd[8][32][17];
    __shared__ int   si[8][32][17];
    int w = threadIdx.x >> 5, lane = threadIdx.x & 31;
    int gid = blockIdx.x * 8 + w;          // 0..8191
    int b = gid >> 10;

    float qx = g_newxyz[gid * 3], qy = g_newxyz[gid * 3 + 1], qz = g_newxyz[gid * 3 + 2];
    const float4* X4 = g_xyzT4 + b * NN;

    float nd[16]; int ni[16];
    #pragma unroll
    for (int j = 0; j < 16; j++) { nd[j] = FLT_MAX; ni[j] = 0x7FFFFFFF; }

    float tau = FLT_MAX;
    for (int i = lane; i < NN; i += 128) {   // 4 points per iter -> MLP 4
        float4 p[4];
        #pragma unroll
        for (int u = 0; u < 4; u++) p[u] = X4[i + u * 32];
        bool ins = false;
        #pragma unroll
        for (int u = 0; u < 4; u++) {
            float dx = __fsub_rn(qx, p[u].x);
            float dy = __fsub_rn(qy, p[u].y);
            float dz = __fsub_rn(qz, p[u].z);
            float d  = __fadd_rn(__fadd_rn(__fmul_rn(dx, dx), __fmul_rn(dy, dy)),
                                 __fmul_rn(dz, dz));
            if (d < tau) {       // warp-wide conservative gate
                float cd = d; int ci = i + u * 32;
                #pragma unroll
                for (int j = 0; j < 16; j++) {
                    if (cd < nd[j]) {
                        float td = nd[j]; int ti = ni[j];
                        nd[j] = cd; ni[j] = ci; cd = td; ci = ti;
                    }
                }
                ins = true;
            }
        }
        if (__any_sync(0xffffffffu, ins))
            tau = __uint_as_float(__reduce_min_sync(0xffffffffu, __float_as_uint(nd[15])));
    }
    #pragma unroll
    for (int j = 0; j < 16; j++) { sd[w][lane][j] = nd[j]; si[w][lane][j] = ni[j]; }
    __syncwarp();

    // 16-round multiway merge of 32 sorted lists (dist asc, tie -> smaller idx)
    int p = 0;
    for (int r = 0; r < 16; r++) {
        float hd = (p < 16) ? sd[w][lane][p] : FLT_MAX;
        int   hi = (p < 16) ? si[w][lane][p] : 0x7FFFFFFF;
        #pragma unroll
        for (int off = 16; off; off >>= 1) {
            float od = __shfl_xor_sync(0xffffffffu, hd, off);
            int   oi = __shfl_xor_sync(0xffffffffu, hi, off);
            if (od < hd || (od == hd && oi < hi)) { hd = od; hi = oi; }
        }
        if (p < 16 && si[w][lane][p] == hi) p++;   // global indices unique -> exact winner
        if (lane == 0) g_knn[gid * 16 + r] = hi;
    }
}

// ---------------- gather + WeightNet MLP + einsum agg: 1 block per point ----------------
__global__ void __launch_bounds__(128) agg_kernel(
    const float* __restrict__ w1, const float* __restrict__ b1,
    const float* __restrict__ w2, const float* __restrict__ b2,
    const float* __restrict__ w3, const float* __restrict__ b3)
{
    __shared__ float feat[KNB][CINC + 1];   // pad to 68
    __shared__ float wts[KNB][WNC];
    __shared__ int   nn[KNB];
    __shared__ float q[3];

    int t = threadIdx.x;
    int pid = blockIdx.x;
    int b = pid >> 10;

    if (t < KNB) nn[t] = g_knn[pid * KNB + t];
    if (t < 3)   q[t]  = g_newxyz[pid * 3 + t];
    __syncthreads();

    if (t < KNB) {
        float4 pp = g_xyzT4[b * NN + nn[t]];
        float gx = pp.x - q[0], gy = pp.y - q[1], gz = pp.z - q[2];
        feat[t][0] = gx; feat[t][1] = gy; feat[t][2] = gz;
        float h1[8], h2[8];
        #pragma unroll
        for (int j = 0; j < 8; j++) {
            float a = b1[j];
            a = fmaf(gx, w1[j], a);
            a = fmaf(gy, w1[8 + j], a);
            a = fmaf(gz, w1[16 + j], a);
            h1[j] = fmaxf(a, 0.f);
        }
        #pragma unroll
        for (int j = 0; j < 8; j++) {
            float a = b2[j];
            #pragma unroll
            for (int i = 0; i < 8; i++) a = fmaf(h1[i], w2[i * 8 + j], a);
            h2[j] = fmaxf(a, 0.f);
        }
        #pragma unroll
        for (int j = 0; j < 16; j++) {
            float a = b3[j];
            #pragma unroll
            for (int i = 0; i < 8; i++) a = fmaf(h2[i], w3[i * 16 + j], a);
            wts[t][j] = fmaxf(a, 0.f);
        }
    }
    // gather neighbor point features (rows contiguous thanks to ptsT)
    for (int idx = t; idx < KNB * DD; idx += 128) {
        int k = idx >> 6, d = idx & 63;
        feat[k][3 + d] = g_ptsT[((size_t)b * NN + nn[k]) * DD + d];
    }
    __syncthreads();

    // agg[c][w] = sum_k feat[k][c] * wts[k][w], flattened j = c*16 + w
    for (int j = t; j < AGGW; j += 128) {
        int c = j >> 4, w = j & 15;
        float a = 0.f;
        #pragma unroll
        for (int k = 0; k < KNB; k++) a = fmaf(feat[k][c], wts[k][w], a);
        g_agg[(size_t)pid * AGGW + j] = a;
    }
}

// ---------------- final linear: GEMM [8192 x 1072] * [1072 x 128] + bias + leaky ----------------
__global__ void __launch_bounds__(256) gemm_kernel(
    const float* __restrict__ lin_w, const float* __restrict__ lin_b,
    float* __restrict__ dout)
{
    __shared__ float As[64][16];
    __shared__ float Bs[16][128];
    int t = threadIdx.x;
    int row0 = blockIdx.x * 64;
    int cg = t & 31, rg = t >> 5;    // 32 col-groups x 8 row-groups

    float acc[8][4];
    #pragma unroll
    for (int i = 0; i < 8; i++)
        #pragma unroll
        for (int j = 0; j < 4; j++) acc[i][j] = 0.f;

    for (int k0 = 0; k0 < AGGW; k0 += 16) {
        __syncthreads();
        {
            int r = t >> 2, kk = (t & 3) << 2;
            float4 v = *(const float4*)&g_agg[(size_t)(row0 + r) * AGGW + k0 + kk];
            *(float4*)&As[r][kk] = v;
        }
        {
            int kk = t >> 5, c = (t & 31) << 2;
            *(float4*)&Bs[kk][c]     = *(const float4*)&lin_w[(size_t)(k0 + kk) * 128 + c];
            *(float4*)&Bs[kk + 8][c] = *(const float4*)&lin_w[(size_t)(k0 + kk + 8) * 128 + c];
        }
        __syncthreads();
        #pragma unroll
        for (int kk = 0; kk < 16; kk++) {
            float4 bv = *(float4*)&Bs[kk][cg << 2];
            #pragma unroll
            for (int ri = 0; ri < 8; ri++) {
                float av = As[rg * 8 + ri][kk];
                acc[ri][0] = fmaf(av, bv.x, acc[ri][0]);
                acc[ri][1] = fmaf(av, bv.y, acc[ri][1]);
                acc[ri][2] = fmaf(av, bv.z, acc[ri][2]);
                acc[ri][3] = fmaf(av, bv.w, acc[ri][3]);
            }
        }
    }
    float bias[4];
    #pragma unroll
    for (int ci = 0; ci < 4; ci++) bias[ci] = lin_b[(cg << 2) + ci];
    #pragma unroll
    for (int ri = 0; ri < 8; ri++) {
        int p = row0 + rg * 8 + ri;
        int b = p >> 10, s = p & 1023;
        #pragma unroll
        for (int ci = 0; ci < 4; ci++) {
            int c = (cg << 2) + ci;
            float v = acc[ri][ci] + bias[ci];
            v = (v > 0.f) ? v : 0.1f * v;             // LeakyReLU(0.1)
            dout[OFF_OUT + ((size_t)b * OUTC + c) * SS + s] = v;
        }
    }
}

// ---------------- launch ----------------
extern "C" void kernel_launch(void* const* d_in, const int* in_sizes, int n_in,
                              void* d_out, int out_size) {
    const float* xyz = (const float*)d_in[0];
    const float* pts = (const float*)d_in[1];
    const float* w1  = (const float*)d_in[2];
    const float* b1  = (const float*)d_in[3];
    const float* w2  = (const float*)d_in[4];
    const float* b2  = (const float*)d_in[5];
    const float* w3  = (const float*)d_in[6];
    const float* b3  = (const float*)d_in[7];
    const float* lw  = (const float*)d_in[8];
    const float* lb  = (const float*)d_in[9];
    float* out = (float*)d_out;

    xyzT_kernel<<<BB * NN / 256, 256>>>(xyz);
    ptsT_kernel<<<dim3(NN / 32, DD / 32, BB), dim3(32, 8)>>>(pts);
    fps_kernel<<<BB, 1024>>>(out);
    knn_kernel<<<BB * SS / 8, 256>>>();
    agg_kernel<<<BB * SS, 128>>>(w1, b1, w2, b2, w3, b3);
    gemm_kernel<<<BB * SS / 64, 256>>>(lw, lb, out);
}

// round 6
// speedup vs baseline: 1.6933x; 1.1654x over previous
#include <cuda_runtime.h>
#include <cfloat>

#define BB   8
#define NN   8192
#define DD   64
#define SS   1024
#define KNB  16          // NSAMPLE
#define WNC  16          // weightnet out channels
#define OUTC 128
#define CINC 67          // 3 + D
#define AGGW (CINC*WNC)  // 1072

#define OFF_OUT (BB*3*SS)                 // 24576
#define OFF_IDX (BB*3*SS + BB*OUTC*SS)    // 1073152

// ---------------- scratch: ONE static device buffer, no allocation ----------------
#define SC_XYZT   0
#define SC_PTST   (SC_XYZT + BB*NN*4)
#define SC_NEWXYZ (SC_PTST + BB*NN*DD)
#define SC_KNN    (SC_NEWXYZ + BB*SS*3)
#define SC_AGG    (SC_KNN + BB*SS*KNB)
#define SC_TOTAL  (SC_AGG + (size_t)BB*SS*AGGW)

__device__ __align__(16) float g_scratch[SC_TOTAL];

#define g_xyzT4  ((float4*)(g_scratch + SC_XYZT))
#define g_ptsT   (g_scratch + SC_PTST)
#define g_newxyz (g_scratch + SC_NEWXYZ)
#define g_knn    ((int*)(g_scratch + SC_KNN))
#define g_agg    (g_scratch + SC_AGG)

// ---------------- packed f32x2 helpers (Blackwell, exact per-element rn) ----------------
__device__ __forceinline__ unsigned long long pk2(float lo, float hi) {
    unsigned long long r;
    asm("mov.b64 %0, {%1, %2};" : "=l"(r) : "f"(lo), "f"(hi));
    return r;
}
__device__ __forceinline__ void upk2(unsigned long long v, float& lo, float& hi) {
    asm("mov.b64 {%0, %1}, %2;" : "=f"(lo), "=f"(hi) : "l"(v));
}
__device__ __forceinline__ unsigned long long addx2(unsigned long long a, unsigned long long b) {
    unsigned long long r;
    asm("add.rn.f32x2 %0, %1, %2;" : "=l"(r) : "l"(a), "l"(b));
    return r;
}
__device__ __forceinline__ unsigned long long mulx2(unsigned long long a, unsigned long long b) {
    unsigned long long r;
    asm("mul.rn.f32x2 %0, %1, %2;" : "=l"(r) : "l"(a), "l"(b));
    return r;
}

// ---------------- layout transforms ----------------
__global__ void xyzT_kernel(const float* __restrict__ xyz) {
    int i = blockIdx.x * 256 + threadIdx.x;     // 0 .. BB*NN-1
    int b = i >> 13, n = i & (NN - 1);
    const float* X = xyz + (size_t)b * 3 * NN;
    g_xyzT4[i] = make_float4(X[n], X[NN + n], X[2 * NN + n], 0.f);
}

__global__ void ptsT_kernel(const float* __restrict__ pts) {
    __shared__ float tile[32][33];
    int b = blockIdx.z;
    int n0 = blockIdx.x * 32, d0 = blockIdx.y * 32;
    int tx = threadIdx.x, ty = threadIdx.y;
    #pragma unroll
    for (int i = 0; i < 32; i += 8)
        tile[ty + i][tx] = pts[(size_t)b * DD * NN + (size_t)(d0 + ty + i) * NN + n0 + tx];
    __syncthreads();
    #pragma unroll
    for (int i = 0; i < 32; i += 8)
        g_ptsT[((size_t)b * NN + n0 + ty + i) * DD + d0 + tx] = tile[tx][ty + i];
}

// ---------------- FPS: 1 block per batch, 1024 threads, 8 pts/thread ----------------
// packed f32x2 distance math (exact rn per element), REDUX argmax reductions,
// ONE barrier per step: double-buffered per-warp results, all warps do level-2.
__global__ void __launch_bounds__(1024, 1) fps_kernel(float* __restrict__ dout) {
    int b = blockIdx.x;
    int t = threadIdx.x;
    int lane = t & 31, warp = t >> 5;

    // pair layout: pair j holds points t + (2j)*1024 and t + (2j+1)*1024
    unsigned long long ppx[4], ppy[4], ppz[4];
    float dist[8];
    #pragma unroll
    for (int j = 0; j < 4; j++) {
        float4 p0 = g_xyzT4[b * NN + t + ((2 * j) << 10)];
        float4 p1 = g_xyzT4[b * NN + t + ((2 * j + 1) << 10)];
        ppx[j] = pk2(p0.x, p1.x);
        ppy[j] = pk2(p0.y, p1.y);
        ppz[j] = pk2(p0.z, p1.z);
        dist[2 * j] = 1e10f; dist[2 * j + 1] = 1e10f;
    }

    __shared__ float    s_bd[2][32];
    __shared__ unsigned s_bi[2][32];

    int far = 0;
    for (int s = 0; s < SS; s++) {
        float4 c = g_xyzT4[b * NN + far];   // broadcast load (L1-resident)
        if (t == 0) {
            dout[b * 3 * SS + s]          = c.x;
            dout[b * 3 * SS + SS + s]     = c.y;
            dout[b * 3 * SS + 2 * SS + s] = c.z;
            dout[OFF_IDX + b * SS + s]    = (float)far;
            int gs = (b * SS + s) * 3;
            g_newxyz[gs] = c.x; g_newxyz[gs + 1] = c.y; g_newxyz[gs + 2] = c.z;
        }
        // negated centroid, packed (exact: rn-add of -c == rn-sub of c)
        unsigned long long ncx = pk2(-c.x, -c.x);
        unsigned long long ncy = pk2(-c.y, -c.y);
        unsigned long long ncz = pk2(-c.z, -c.z);

        float bd = 0.0f; unsigned bi = 0x7fffffffu;
        #pragma unroll
        for (int j = 0; j < 4; j++) {
            unsigned long long dx = addx2(ppx[j], ncx);
            unsigned long long dy = addx2(ppy[j], ncy);
            unsigned long long dz = addx2(ppz[j], ncz);
            unsigned long long xx = mulx2(dx, dx);
            unsigned long long yy = mulx2(dy, dy);
            unsigned long long s1 = addx2(xx, yy);
            unsigned long long zz = mulx2(dz, dz);
            unsigned long long dd = addx2(s1, zz);
            float d0, d1;
            upk2(dd, d0, d1);
            float n0 = fminf(dist[2 * j], d0);     dist[2 * j] = n0;
            if (n0 > bd) { bd = n0; bi = (unsigned)(t + ((2 * j) << 10)); }
            float n1 = fminf(dist[2 * j + 1], d1); dist[2 * j + 1] = n1;
            if (n1 > bd) { bd = n1; bi = (unsigned)(t + ((2 * j + 1) << 10)); }
        }
        // warp argmax via REDUX: dist >= 0 so float bits order as u32; tie -> min index
        unsigned mb   = __float_as_uint(bd);
        unsigned wmax = __reduce_max_sync(0xffffffffu, mb);
        unsigned cand = (mb == wmax) ? bi : 0xffffffffu;
        unsigned wbi  = __reduce_min_sync(0xffffffffu, cand);
        if (lane == 0) { s_bd[s & 1][warp] = __uint_as_float(wmax); s_bi[s & 1][warp] = wbi; }
        __syncthreads();
        // level-2: every warp reduces the 32 per-warp results itself (no 2nd barrier;
        // double-buffering makes the next step's writes race-free)
        unsigned vb = __float_as_uint(s_bd[s & 1][lane]);
        unsigned vi = s_bi[s & 1][lane];
        unsigned gmax = __reduce_max_sync(0xffffffffu, vb);
        unsigned gc   = (vb == gmax) ? vi : 0xffffffffu;
        far = (int)__reduce_min_sync(0xffffffffu, gc);
    }
}

// ---------------- KNN: 1 warp per sampled point, warp-collective exact top-16 ----------------
// The current top-16 (by dist asc, tie idx asc) lives one entry per lane in lanes 0..15.
// Gate is EXACT (vs the true worst), so insert events are rare (~120/query total).
// Insertions process passing lanes in lane order == index order (stable top-k semantics).
__global__ void __launch_bounds__(512) knn_kernel() {
    int w = threadIdx.x >> 5, lane = threadIdx.x & 31;
    int gid = blockIdx.x * 16 + w;          // 0..8191
    int b = gid >> 10;

    float qx = g_newxyz[gid * 3], qy = g_newxyz[gid * 3 + 1], qz = g_newxyz[gid * 3 + 2];
    const float4* X4 = g_xyzT4 + b * NN;

    float st_d = FLT_MAX;            // stored entry (meaningful in lanes 0..15)
    int   st_i = 0x7FFFFFFF;
    float worst_d = FLT_MAX;         // warp-uniform: max dist among stored, tie max idx
    int   worst_i = 0x7FFFFFFF;

    for (int i = lane; i < NN; i += 32) {
        float4 p = X4[i];
        float dx = __fsub_rn(qx, p.x);
        float dy = __fsub_rn(qy, p.y);
        float dz = __fsub_rn(qz, p.z);
        float d  = __fadd_rn(__fadd_rn(__fmul_rn(dx, dx), __fmul_rn(dy, dy)),
                             __fmul_rn(dz, dz));
        bool pass = (d < worst_d) || (d == worst_d && i < worst_i);
        unsigned mask = __ballot_sync(0xffffffffu, pass);
        while (mask) {                       // warp-uniform loop
            int src = __ffs(mask) - 1; mask &= mask - 1;
            float dc = __shfl_sync(0xffffffffu, d, src);
            int   ic = __shfl_sync(0xffffffffu, i, src);
            if (dc < worst_d || (dc == worst_d && ic < worst_i)) {   // uniform re-check
                // evict the worst lane (matches worst_d, worst_i)
                bool meq = (lane < 16) && (st_d == worst_d) && (st_i == worst_i);
                unsigned bl = __ballot_sync(0xffffffffu, meq);
                int wl = __ffs(bl) - 1;
                if (lane == wl) { st_d = dc; st_i = ic; }
                // recompute worst (dist >= 0 so float bits order as u32)
                unsigned db = (lane < 16) ? __float_as_uint(st_d) : 0u;
                unsigned wd = __reduce_max_sync(0xffffffffu, db);
                unsigned ci = (db == wd && lane < 16) ? (unsigned)st_i : 0u;
                unsigned wi = __reduce_max_sync(0xffffffffu, ci);
                worst_d = __uint_as_float(wd);
                worst_i = (int)wi;
            }
        }
    }
    // emit sorted ascending (dist, then idx): 16 rounds of min-extraction
    bool act = (lane < 16);
    #pragma unroll 1
    for (int r = 0; r < 16; r++) {
        unsigned db = act ? __float_as_uint(st_d) : 0xFFFFFFFFu;
        unsigned md = __reduce_min_sync(0xffffffffu, db);
        unsigned ib = (act && db == md) ? (unsigned)st_i : 0xFFFFFFFFu;
        unsigned mi = __reduce_min_sync(0xffffffffu, ib);
        if (act && db == md && (unsigned)st_i == mi) {
            g_knn[gid * 16 + r] = st_i;
            act = false;
        }
    }
}

// ---------------- gather + WeightNet MLP + einsum agg: 1 block per point ----------------
__global__ void __launch_bounds__(128) agg_kernel(
    const float* __restrict__ w1, const float* __restrict__ b1,
    const float* __restrict__ w2, const float* __restrict__ b2,
    const float* __restrict__ w3, const float* __restrict__ b3)
{
    __shared__ float feat[KNB][CINC + 1];   // pad to 68
    __shared__ float wts[KNB][WNC];
    __shared__ int   nn[KNB];
    __shared__ float q[3];

    int t = threadIdx.x;
    int pid = blockIdx.x;
    int b = pid >> 10;

    if (t < KNB) nn[t] = g_knn[pid * KNB + t];
    if (t < 3)   q[t]  = g_newxyz[pid * 3 + t];
    __syncthreads();

    if (t < KNB) {
        float4 pp = g_xyzT4[b * NN + nn[t]];
        float gx = pp.x - q[0], gy = pp.y - q[1], gz = pp.z - q[2];
        feat[t][0] = gx; feat[t][1] = gy; feat[t][2] = gz;
        float h1[8], h2[8];
        #pragma unroll
        for (int j = 0; j < 8; j++) {
            float a = b1[j];
            a = fmaf(gx, w1[j], a);
            a = fmaf(gy, w1[8 + j], a);
            a = fmaf(gz, w1[16 + j], a);
            h1[j] = fmaxf(a, 0.f);
        }
        #pragma unroll
        for (int j = 0; j < 8; j++) {
            float a = b2[j];
            #pragma unroll
            for (int i = 0; i < 8; i++) a = fmaf(h1[i], w2[i * 8 + j], a);
            h2[j] = fmaxf(a, 0.f);
        }
        #pragma unroll
        for (int j = 0; j < 16; j++) {
            float a = b3[j];
            #pragma unroll
            for (int i = 0; i < 8; i++) a = fmaf(h2[i], w3[i * 16 + j], a);
            wts[t][j] = fmaxf(a, 0.f);
        }
    }
    // gather neighbor point features (rows contiguous thanks to ptsT)
    for (int idx = t; idx < KNB * DD; idx += 128) {
        int k = idx >> 6, d = idx & 63;
        feat[k][3 + d] = g_ptsT[((size_t)b * NN + nn[k]) * DD + d];
    }
    __syncthreads();

    // agg[c][w] = sum_k feat[k][c] * wts[k][w], flattened j = c*16 + w
    for (int j = t; j < AGGW; j += 128) {
        int c = j >> 4, w = j & 15;
        float a = 0.f;
        #pragma unroll
        for (int k = 0; k < KNB; k++) a = fmaf(feat[k][c], wts[k][w], a);
        g_agg[(size_t)pid * AGGW + j] = a;
    }
}

// ---------------- final linear: GEMM [8192 x 1072] * [1072 x 128] + bias + leaky ----------------
__global__ void __launch_bounds__(256) gemm_kernel(
    const float* __restrict__ lin_w, const float* __restrict__ lin_b,
    float* __restrict__ dout)
{
    __shared__ float As[64][16];
    __shared__ float Bs[16][128];
    int t = threadIdx.x;
    int row0 = blockIdx.x * 64;
    int cg = t & 31, rg = t >> 5;    // 32 col-groups x 8 row-groups

    float acc[8][4];
    #pragma unroll
    for (int i = 0; i < 8; i++)
        #pragma unroll
        for (int j = 0; j < 4; j++) acc[i][j] = 0.f;

    for (int k0 = 0; k0 < AGGW; k0 += 16) {
        __syncthreads();
        {
            int r = t >> 2, kk = (t & 3) << 2;
            float4 v = *(const float4*)&g_agg[(size_t)(row0 + r) * AGGW + k0 + kk];
            *(float4*)&As[r][kk] = v;
        }
        {
            int kk = t >> 5, c = (t & 31) << 2;
            *(float4*)&Bs[kk][c]     = *(const float4*)&lin_w[(size_t)(k0 + kk) * 128 + c];
            *(float4*)&Bs[kk + 8][c] = *(const float4*)&lin_w[(size_t)(k0 + kk + 8) * 128 + c];
        }
        __syncthreads();
        #pragma unroll
        for (int kk = 0; kk < 16; kk++) {
            float4 bv = *(float4*)&Bs[kk][cg << 2];
            #pragma unroll
            for (int ri = 0; ri < 8; ri++) {
                float av = As[rg * 8 + ri][kk];
                acc[ri][0] = fmaf(av, bv.x, acc[ri][0]);
                acc[ri][1] = fmaf(av, bv.y, acc[ri][1]);
                acc[ri][2] = fmaf(av, bv.z, acc[ri][2]);
                acc[ri][3] = fmaf(av, bv.w, acc[ri][3]);
            }
        }
    }
    float bias[4];
    #pragma unroll
    for (int ci = 0; ci < 4; ci++) bias[ci] = lin_b[(cg << 2) + ci];
    #pragma unroll
    for (int ri = 0; ri < 8; ri++) {
        int p = row0 + rg * 8 + ri;
        int b = p >> 10, s = p & 1023;
        #pragma unroll
        for (int ci = 0; ci < 4; ci++) {
            int c = (cg << 2) + ci;
            float v = acc[ri][ci] + bias[ci];
            v = (v > 0.f) ? v : 0.1f * v;             // LeakyReLU(0.1)
            dout[OFF_OUT + ((size_t)b * OUTC + c) * SS + s] = v;
        }
    }
}

// ---------------- launch ----------------
extern "C" void kernel_launch(void* const* d_in, const int* in_sizes, int n_in,
                              void* d_out, int out_size) {
    const float* xyz = (const float*)d_in[0];
    const float* pts = (const float*)d_in[1];
    const float* w1  = (const float*)d_in[2];
    const float* b1  = (const float*)d_in[3];
    const float* w2  = (const float*)d_in[4];
    const float* b2  = (const float*)d_in[5];
    const float* w3  = (const float*)d_in[6];
    const float* b3  = (const float*)d_in[7];
    const float* lw  = (const float*)d_in[8];
    const float* lb  = (const float*)d_in[9];
    float* out = (float*)d_out;

    xyzT_kernel<<<BB * NN / 256, 256>>>(xyz);
    ptsT_kernel<<<dim3(NN / 32, DD / 32, BB), dim3(32, 8)>>>(pts);
    fps_kernel<<<BB, 1024>>>(out);
    knn_kernel<<<BB * SS / 16, 512>>>();
    agg_kernel<<<BB * SS, 128>>>(w1, b1, w2, b2, w3, b3);
    gemm_kernel<<<BB * SS / 64, 256>>>(lw, lb, out);
}